// round 2
// baseline (speedup 1.0000x reference)
#include <cuda_runtime.h>
#include <cstdint>

// Problem constants
#define BB 16
#define NN 96
#define DD 256
#define MROWS (BB * NN * NN)          // 147456
#define NCOLS (NN * DD)               // 24576 (per-batch cols in message passing)

// Scratch (allocation-free: static device globals)
__device__ float g_h1[(size_t)MROWS * DD];
__device__ float g_h2[(size_t)MROWS * DD];

// ---------------------------------------------------------------------------
// Kernel 1/2: C[M,256] = act( A[M,256] @ W[256,256] + bias ), optional row mask
// Tile: BM=128, BN=128, BK=16; 256 threads; 8x8 per-thread microtile.
// ---------------------------------------------------------------------------
__global__ __launch_bounds__(256)
void mlp_gemm_relu(const float* __restrict__ A,
                   const float* __restrict__ W,
                   const float* __restrict__ bias,
                   const int* __restrict__ mask,   // int32 bool; nullptr => no mask
                   float* __restrict__ C)
{
    const int BM = 128, BN = 128, BK = 16;
    __shared__ float As[BK][BM];   // transposed A tile
    __shared__ float Ws[BK][BN];

    const int tid = threadIdx.x;
    const int tx = tid & 15;       // 0..15 -> 8 output cols each
    const int ty = tid >> 4;       // 0..15 -> 8 output rows each
    const long rowBase = (long)blockIdx.y * BM;
    const int  colBase = blockIdx.x * BN;

    float acc[8][8];
#pragma unroll
    for (int i = 0; i < 8; i++)
#pragma unroll
        for (int j = 0; j < 8; j++) acc[i][j] = 0.0f;

    for (int kt = 0; kt < DD; kt += BK) {
        // --- load A tile: 128x16 = 512 float4, 2 per thread, store transposed
#pragma unroll
        for (int r = 0; r < 2; r++) {
            int i    = tid + r * 256;       // 0..511
            int arow = i >> 2;              // 4 float4 per row (16 cols)
            int ac4  = i & 3;
            float4 v = *reinterpret_cast<const float4*>(
                A + (rowBase + arow) * DD + kt + ac4 * 4);
            As[ac4 * 4 + 0][arow] = v.x;
            As[ac4 * 4 + 1][arow] = v.y;
            As[ac4 * 4 + 2][arow] = v.z;
            As[ac4 * 4 + 3][arow] = v.w;
        }
        // --- load W tile: 16x128 = 512 float4, 2 per thread
#pragma unroll
        for (int r = 0; r < 2; r++) {
            int i    = tid + r * 256;
            int wrow = i >> 5;              // 32 float4 per row (128 cols)
            int wc4  = i & 31;
            *reinterpret_cast<float4*>(&Ws[wrow][wc4 * 4]) =
                *reinterpret_cast<const float4*>(
                    W + (size_t)(kt + wrow) * DD + colBase + wc4 * 4);
        }
        __syncthreads();

#pragma unroll
        for (int k = 0; k < BK; k++) {
            float ra[8], rw[8];
#pragma unroll
            for (int i = 0; i < 8; i++) ra[i] = As[k][ty * 8 + i];
#pragma unroll
            for (int j = 0; j < 8; j++) rw[j] = Ws[k][tx * 8 + j];
#pragma unroll
            for (int i = 0; i < 8; i++)
#pragma unroll
                for (int j = 0; j < 8; j++) acc[i][j] += ra[i] * rw[j];
        }
        __syncthreads();
    }

    // --- epilogue: bias + relu (+ row mask), store
#pragma unroll
    for (int i = 0; i < 8; i++) {
        long r = rowBase + ty * 8 + i;
        float mval = 1.0f;
        if (mask != nullptr) mval = (mask[r] != 0) ? 1.0f : 0.0f;
#pragma unroll
        for (int j = 0; j < 8; j++) {
            int cn  = colBase + tx * 8 + j;
            float v = acc[i][j] + bias[cn];
            v = fmaxf(v, 0.0f);
            C[r * DD + cn] = v * mval;
        }
    }
}

// ---------------------------------------------------------------------------
// Kernel 3: per-batch  Out[b] (96 x 24576) = Aadj[b] (96x96) @ H[b] (96x24576)
// Tile: BM=96 (whole M), BN=128, BK=32; 256 threads; 6x8 per-thread microtile.
// grid = (NCOLS/128, B)
// ---------------------------------------------------------------------------
__global__ __launch_bounds__(256)
void msgpass_gemm(const float* __restrict__ Aadj,
                  const float* __restrict__ H,
                  float* __restrict__ Out)
{
    const int BN = 128, BK = 32, KTOT = NN;   // 96
    __shared__ float As[BK][NN];   // transposed A tile: [k][m]
    __shared__ float Bs[BK][BN];

    const int b = blockIdx.y;
    const int colBase = blockIdx.x * BN;
    const float* Ab = Aadj + (size_t)b * NN * NN;
    const float* Hb = H    + (size_t)b * NN * NCOLS;
    float*       Ob = Out  + (size_t)b * NN * NCOLS;

    const int tid = threadIdx.x;
    const int tx = tid & 15;      // 8 cols each
    const int ty = tid >> 4;      // 6 rows each

    float acc[6][8];
#pragma unroll
    for (int i = 0; i < 6; i++)
#pragma unroll
        for (int j = 0; j < 8; j++) acc[i][j] = 0.0f;

    for (int kt = 0; kt < KTOT; kt += BK) {
        // --- A tile: 96x32 = 768 float4, 3 per thread, transposed
#pragma unroll
        for (int r = 0; r < 3; r++) {
            int i    = tid + r * 256;      // 0..767
            int arow = i >> 3;             // 8 float4 per row (32 cols)
            int ac4  = i & 7;
            float4 v = *reinterpret_cast<const float4*>(
                Ab + arow * NN + kt + ac4 * 4);
            As[ac4 * 4 + 0][arow] = v.x;
            As[ac4 * 4 + 1][arow] = v.y;
            As[ac4 * 4 + 2][arow] = v.z;
            As[ac4 * 4 + 3][arow] = v.w;
        }
        // --- B tile: 32x128 = 1024 float4, 4 per thread
#pragma unroll
        for (int r = 0; r < 4; r++) {
            int i    = tid + r * 256;
            int brow = i >> 5;             // 32 float4 per row
            int bc4  = i & 31;
            *reinterpret_cast<float4*>(&Bs[brow][bc4 * 4]) =
                *reinterpret_cast<const float4*>(
                    Hb + (size_t)(kt + brow) * NCOLS + colBase + bc4 * 4);
        }
        __syncthreads();

#pragma unroll
        for (int k = 0; k < BK; k++) {
            float ra[6], rw[8];
#pragma unroll
            for (int i = 0; i < 6; i++) ra[i] = As[k][ty * 6 + i];
#pragma unroll
            for (int j = 0; j < 8; j++) rw[j] = Bs[k][tx * 8 + j];
#pragma unroll
            for (int i = 0; i < 6; i++)
#pragma unroll
                for (int j = 0; j < 8; j++) acc[i][j] += ra[i] * rw[j];
        }
        __syncthreads();
    }

#pragma unroll
    for (int i = 0; i < 6; i++) {
        int row = ty * 6 + i;
#pragma unroll
        for (int j = 0; j < 8; j++) {
            int col = colBase + tx * 8 + j;
            Ob[(size_t)row * NCOLS + col] = acc[i][j];
        }
    }
}

// ---------------------------------------------------------------------------
// kernel_launch: inputs in order X, mask, A, W1, b1, W2, b2
// ---------------------------------------------------------------------------
extern "C" void kernel_launch(void* const* d_in, const int* in_sizes, int n_in,
                              void* d_out, int out_size)
{
    const float* X    = (const float*)d_in[0];
    const int*   mask = (const int*)d_in[1];    // bool materialized as int32
    const float* Aadj = (const float*)d_in[2];
    const float* W1   = (const float*)d_in[3];
    const float* b1   = (const float*)d_in[4];
    const float* W2   = (const float*)d_in[5];
    const float* b2   = (const float*)d_in[6];
    float*       out  = (float*)d_out;

    float* h1;
    float* h2;
    cudaGetSymbolAddress((void**)&h1, g_h1);
    cudaGetSymbolAddress((void**)&h2, g_h2);

    // Layer 1: h1 = relu(X @ W1 + b1)
    {
        dim3 grid(DD / 128, MROWS / 128);   // (2, 1152)
        mlp_gemm_relu<<<grid, 256>>>(X, W1, b1, nullptr, h1);
    }
    // Layer 2: h2 = mask * relu(h1 @ W2 + b2)
    {
        dim3 grid(DD / 128, MROWS / 128);
        mlp_gemm_relu<<<grid, 256>>>(h1, W2, b2, mask, h2);
    }
    // Message passing: out[b] = Aadj[b] @ h2[b]
    {
        dim3 grid(NCOLS / 128, BB);         // (192, 16)
        msgpass_gemm<<<grid, 256>>>(Aadj, h2, out);
    }
}

// round 3
// speedup vs baseline: 2.8202x; 2.8202x over previous
#include <cuda_runtime.h>
#include <cstdint>
#include <cstddef>

#define BB 16
#define NN 96
#define DD 256
#define MROWS (BB * NN * NN)          // 147456
#define NCOLS (NN * DD)               // 24576

// Scratch (allocation-free device globals)
__device__ float g_Xr[(size_t)MROWS * DD];   // rounded X
__device__ float g_h1[(size_t)MROWS * DD];   // rounded h1
__device__ float g_h2[(size_t)MROWS * DD];   // rounded h2
__device__ float g_W1r[DD * DD];
__device__ float g_W2r[DD * DD];
__device__ float g_Ar[BB * NN * NN];

// ---------------------------------------------------------------------------
// helpers
// ---------------------------------------------------------------------------
__device__ __forceinline__ float tf32r(float x) {
    unsigned u;
    asm("cvt.rna.tf32.f32 %0, %1;" : "=r"(u) : "f"(x));
    return __uint_as_float(u);
}

__device__ __forceinline__ void mma8(float* c, const unsigned* a, const unsigned* b) {
    asm("mma.sync.aligned.m16n8k8.row.col.f32.tf32.tf32.f32 "
        "{%0,%1,%2,%3}, {%4,%5,%6,%7}, {%8,%9}, {%0,%1,%2,%3};"
        : "+f"(c[0]), "+f"(c[1]), "+f"(c[2]), "+f"(c[3])
        : "r"(a[0]), "r"(a[1]), "r"(a[2]), "r"(a[3]), "r"(b[0]), "r"(b[1]));
}

// ---------------------------------------------------------------------------
// elementwise round-to-tf32 prepass
// ---------------------------------------------------------------------------
__global__ void round_tf32_kernel(const float4* __restrict__ src,
                                  float4* __restrict__ dst, int n4) {
    int i = blockIdx.x * blockDim.x + threadIdx.x;
    if (i < n4) {
        float4 v = src[i];
        v.x = tf32r(v.x); v.y = tf32r(v.y); v.z = tf32r(v.z); v.w = tf32r(v.w);
        dst[i] = v;
    }
}

// ---------------------------------------------------------------------------
// MLP GEMM: C[M,256] = act(A[M,256] @ W[256,256] + bias), optional row mask.
// BM=128 BN=128 BK=32, 256 threads (8 warps), warp tile 64x32 (4 m16 x 4 n8).
// SMEM: chunk-XOR swizzled, conflict-free fragment LDS.
// ---------------------------------------------------------------------------
__global__ __launch_bounds__(256)
void mlp_mma(const float* __restrict__ A, const float* __restrict__ W,
             const float* __restrict__ bias, const int* __restrict__ mask,
             float* __restrict__ C, int roundOut)
{
    __shared__ float As[128 * 32];   // [m][k], 8 chunks/row, pch = ch ^ (m&7)
    __shared__ float Bs[32 * 128];   // [k][n], 32 chunks/row, pch = ch ^ (k&7)

    const int tid  = threadIdx.x;
    const int lane = tid & 31;
    const int warp = tid >> 5;
    const int grp  = lane >> 2;          // 0..7
    const int c4   = lane & 3;           // 0..3
    const int wm   = warp >> 2;          // 0..1
    const int wn   = warp & 3;           // 0..3
    const int warpM = wm * 64;
    const int warpN = wn * 32;
    const int rowBase = blockIdx.y * 128;
    const int colBase = blockIdx.x * 128;

    // loader indices (4 float4 each for A and B per tile)
    const int ar0 = tid >> 3;            // A row base (+32 per t)
    const int af4 = tid & 7;             // A float4-chunk within row
    const int kr0 = tid >> 5;            // B k-row base (+8 per t)
    const int nf4 = tid & 31;            // B float4-chunk within row

    const int aPch = (af4 ^ (ar0 & 7)) << 2;   // constant per thread
    const int bPch = (nf4 ^ (kr0 & 7)) << 2;

    float4 stA[4], stB[4];

    // prologue LDG (tile 0)
#pragma unroll
    for (int t = 0; t < 4; t++)
        stA[t] = *reinterpret_cast<const float4*>(
            A + (size_t)(rowBase + ar0 + 32 * t) * DD + af4 * 4);
#pragma unroll
    for (int t = 0; t < 4; t++)
        stB[t] = *reinterpret_cast<const float4*>(
            W + (size_t)(kr0 + 8 * t) * DD + colBase + nf4 * 4);

    float acc[4][4][4];
#pragma unroll
    for (int i = 0; i < 4; i++)
#pragma unroll
        for (int j = 0; j < 4; j++)
#pragma unroll
            for (int r = 0; r < 4; r++) acc[i][j][r] = 0.0f;

#pragma unroll 1
    for (int it = 0; it < 8; it++) {
        if (it) __syncthreads();
        // STS staged tile
#pragma unroll
        for (int t = 0; t < 4; t++)
            *reinterpret_cast<float4*>(&As[(ar0 + 32 * t) * 32 + aPch]) = stA[t];
#pragma unroll
        for (int t = 0; t < 4; t++)
            *reinterpret_cast<float4*>(&Bs[(kr0 + 8 * t) * 128 + bPch]) = stB[t];
        __syncthreads();

        // prefetch next tile
        if (it < 7) {
            int kt = (it + 1) * 32;
#pragma unroll
            for (int t = 0; t < 4; t++)
                stA[t] = *reinterpret_cast<const float4*>(
                    A + (size_t)(rowBase + ar0 + 32 * t) * DD + kt + af4 * 4);
#pragma unroll
            for (int t = 0; t < 4; t++)
                stB[t] = *reinterpret_cast<const float4*>(
                    W + (size_t)(kt + kr0 + 8 * t) * DD + colBase + nf4 * 4);
        }

        // compute: 4 k8-steps
#pragma unroll
        for (int s = 0; s < 4; s++) {
            unsigned af[4][4];
#pragma unroll
            for (int mt = 0; mt < 4; mt++) {
                int r  = warpM + mt * 16 + grp;
                int r8 = r + 8;
                af[mt][0] = __float_as_uint(As[r  * 32 + (((2 * s)     ^ (r  & 7)) << 2) + c4]);
                af[mt][1] = __float_as_uint(As[r8 * 32 + (((2 * s)     ^ (r8 & 7)) << 2) + c4]);
                af[mt][2] = __float_as_uint(As[r  * 32 + (((2 * s + 1) ^ (r  & 7)) << 2) + c4]);
                af[mt][3] = __float_as_uint(As[r8 * 32 + (((2 * s + 1) ^ (r8 & 7)) << 2) + c4]);
            }
            unsigned bf[4][2];
#pragma unroll
            for (int nt = 0; nt < 4; nt++) {
                int n  = warpN + nt * 8 + grp;
                int k0 = c4 + 8 * s;
                int k1 = k0 + 4;
                bf[nt][0] = __float_as_uint(Bs[k0 * 128 + (((n >> 2) ^ (k0 & 7)) << 2) + (n & 3)]);
                bf[nt][1] = __float_as_uint(Bs[k1 * 128 + (((n >> 2) ^ (k1 & 7)) << 2) + (n & 3)]);
            }
#pragma unroll
            for (int mt = 0; mt < 4; mt++)
#pragma unroll
                for (int nt = 0; nt < 4; nt++)
                    mma8(acc[mt][nt], af[mt], bf[nt]);
        }
    }

    // epilogue: bias + relu (+mask), optional round-to-tf32 for next layer
#pragma unroll
    for (int mt = 0; mt < 4; mt++) {
        int rr = rowBase + warpM + mt * 16 + grp;
#pragma unroll
        for (int pr = 0; pr < 2; pr++) {
            int r = rr + 8 * pr;
            float mv = 1.0f;
            if (mask != nullptr) mv = (mask[r] != 0) ? 1.0f : 0.0f;
#pragma unroll
            for (int nt = 0; nt < 4; nt++) {
                int col = colBase + warpN + nt * 8 + 2 * c4;
                float2 bb = *reinterpret_cast<const float2*>(bias + col);
                float v0 = fmaxf(acc[mt][nt][2 * pr + 0] + bb.x, 0.0f) * mv;
                float v1 = fmaxf(acc[mt][nt][2 * pr + 1] + bb.y, 0.0f) * mv;
                if (roundOut) { v0 = tf32r(v0); v1 = tf32r(v1); }
                *reinterpret_cast<float2*>(C + (size_t)r * DD + col) = make_float2(v0, v1);
            }
        }
    }
}

// ---------------------------------------------------------------------------
// Message passing: Out[b] (96 x 24576) = Ar[b] (96x96) @ H[b] (96x24576)
// BM=96 (full M), BN=128, BK=32, K=96. 256 threads, warp tile 48x32 (3 m16 x 4 n8).
// ---------------------------------------------------------------------------
__global__ __launch_bounds__(256)
void msg_mma(const float* __restrict__ Ar, const float* __restrict__ H,
             float* __restrict__ Out)
{
    __shared__ float As[96 * 32];
    __shared__ float Bs[32 * 128];

    const int b = blockIdx.y;
    const float* Ab = Ar + (size_t)b * NN * NN;
    const float* Hb = H  + (size_t)b * NN * NCOLS;
    float*       Ob = Out + (size_t)b * NN * NCOLS;

    const int tid  = threadIdx.x;
    const int lane = tid & 31;
    const int warp = tid >> 5;
    const int grp  = lane >> 2;
    const int c4   = lane & 3;
    const int wm   = warp >> 2;          // 0..1
    const int wn   = warp & 3;           // 0..3
    const int warpM = wm * 48;
    const int warpN = wn * 32;
    const int colBase = blockIdx.x * 128;

    const int ar0 = tid >> 3;            // +32 per t, t<3 -> rows 0..95
    const int af4 = tid & 7;
    const int kr0 = tid >> 5;
    const int nf4 = tid & 31;
    const int aPch = (af4 ^ (ar0 & 7)) << 2;
    const int bPch = (nf4 ^ (kr0 & 7)) << 2;

    float4 stA[3], stB[4];
#pragma unroll
    for (int t = 0; t < 3; t++)
        stA[t] = *reinterpret_cast<const float4*>(
            Ab + (size_t)(ar0 + 32 * t) * NN + af4 * 4);
#pragma unroll
    for (int t = 0; t < 4; t++)
        stB[t] = *reinterpret_cast<const float4*>(
            Hb + (size_t)(kr0 + 8 * t) * NCOLS + colBase + nf4 * 4);

    float acc[3][4][4];
#pragma unroll
    for (int i = 0; i < 3; i++)
#pragma unroll
        for (int j = 0; j < 4; j++)
#pragma unroll
            for (int r = 0; r < 4; r++) acc[i][j][r] = 0.0f;

#pragma unroll 1
    for (int it = 0; it < 3; it++) {
        if (it) __syncthreads();
#pragma unroll
        for (int t = 0; t < 3; t++)
            *reinterpret_cast<float4*>(&As[(ar0 + 32 * t) * 32 + aPch]) = stA[t];
#pragma unroll
        for (int t = 0; t < 4; t++)
            *reinterpret_cast<float4*>(&Bs[(kr0 + 8 * t) * 128 + bPch]) = stB[t];
        __syncthreads();

        if (it < 2) {
            int kt = (it + 1) * 32;
#pragma unroll
            for (int t = 0; t < 3; t++)
                stA[t] = *reinterpret_cast<const float4*>(
                    Ab + (size_t)(ar0 + 32 * t) * NN + kt + af4 * 4);
#pragma unroll
            for (int t = 0; t < 4; t++)
                stB[t] = *reinterpret_cast<const float4*>(
                    Hb + (size_t)(kt + kr0 + 8 * t) * NCOLS + colBase + nf4 * 4);
        }

#pragma unroll
        for (int s = 0; s < 4; s++) {
            unsigned af[3][4];
#pragma unroll
            for (int mt = 0; mt < 3; mt++) {
                int r  = warpM + mt * 16 + grp;
                int r8 = r + 8;
                af[mt][0] = __float_as_uint(As[r  * 32 + (((2 * s)     ^ (r  & 7)) << 2) + c4]);
                af[mt][1] = __float_as_uint(As[r8 * 32 + (((2 * s)     ^ (r8 & 7)) << 2) + c4]);
                af[mt][2] = __float_as_uint(As[r  * 32 + (((2 * s + 1) ^ (r  & 7)) << 2) + c4]);
                af[mt][3] = __float_as_uint(As[r8 * 32 + (((2 * s + 1) ^ (r8 & 7)) << 2) + c4]);
            }
            unsigned bf[4][2];
#pragma unroll
            for (int nt = 0; nt < 4; nt++) {
                int n  = warpN + nt * 8 + grp;
                int k0 = c4 + 8 * s;
                int k1 = k0 + 4;
                bf[nt][0] = __float_as_uint(Bs[k0 * 128 + (((n >> 2) ^ (k0 & 7)) << 2) + (n & 3)]);
                bf[nt][1] = __float_as_uint(Bs[k1 * 128 + (((n >> 2) ^ (k1 & 7)) << 2) + (n & 3)]);
            }
#pragma unroll
            for (int mt = 0; mt < 3; mt++)
#pragma unroll
                for (int nt = 0; nt < 4; nt++)
                    mma8(acc[mt][nt], af[mt], bf[nt]);
        }
    }

#pragma unroll
    for (int mt = 0; mt < 3; mt++) {
        int rr = warpM + mt * 16 + grp;
#pragma unroll
        for (int pr = 0; pr < 2; pr++) {
            int r = rr + 8 * pr;
#pragma unroll
            for (int nt = 0; nt < 4; nt++) {
                int col = colBase + warpN + nt * 8 + 2 * c4;
                *reinterpret_cast<float2*>(Ob + (size_t)r * NCOLS + col) =
                    make_float2(acc[mt][nt][2 * pr + 0], acc[mt][nt][2 * pr + 1]);
            }
        }
    }
}

// ---------------------------------------------------------------------------
// kernel_launch: inputs X, mask, A, W1, b1, W2, b2
// ---------------------------------------------------------------------------
extern "C" void kernel_launch(void* const* d_in, const int* in_sizes, int n_in,
                              void* d_out, int out_size)
{
    const float* X    = (const float*)d_in[0];
    const int*   mask = (const int*)d_in[1];
    const float* Aadj = (const float*)d_in[2];
    const float* W1   = (const float*)d_in[3];
    const float* b1   = (const float*)d_in[4];
    const float* W2   = (const float*)d_in[5];
    const float* b2   = (const float*)d_in[6];
    float*       out  = (float*)d_out;

    float *xr, *h1, *h2, *w1r, *w2r, *ar;
    cudaGetSymbolAddress((void**)&xr,  g_Xr);
    cudaGetSymbolAddress((void**)&h1,  g_h1);
    cudaGetSymbolAddress((void**)&h2,  g_h2);
    cudaGetSymbolAddress((void**)&w1r, g_W1r);
    cudaGetSymbolAddress((void**)&w2r, g_W2r);
    cudaGetSymbolAddress((void**)&ar,  g_Ar);

    // prepass: round-to-nearest tf32 on all GEMM inputs
    {
        int n4 = (MROWS * DD) / 4;
        round_tf32_kernel<<<(n4 + 255) / 256, 256>>>((const float4*)X, (float4*)xr, n4);
        int w4 = (DD * DD) / 4;
        round_tf32_kernel<<<(w4 + 255) / 256, 256>>>((const float4*)W1, (float4*)w1r, w4);
        round_tf32_kernel<<<(w4 + 255) / 256, 256>>>((const float4*)W2, (float4*)w2r, w4);
        int a4 = (BB * NN * NN) / 4;
        round_tf32_kernel<<<(a4 + 255) / 256, 256>>>((const float4*)Aadj, (float4*)ar, a4);
    }

    // layer 1: h1 = round(relu(Xr @ W1r + b1))
    {
        dim3 grid(DD / 128, MROWS / 128);   // (2, 1152)
        mlp_mma<<<grid, 256>>>(xr, w1r, b1, nullptr, h1, 1);
    }
    // layer 2: h2 = round(mask * relu(h1 @ W2r + b2))
    {
        dim3 grid(DD / 128, MROWS / 128);
        mlp_mma<<<grid, 256>>>(h1, w2r, b2, mask, h2, 1);
    }
    // message passing: out[b] = Ar[b] @ h2[b]
    {
        dim3 grid(NCOLS / 128, BB);         // (192, 16)
        msg_mma<<<grid, 256>>>(ar, h2, out);
    }
}

// round 4
// speedup vs baseline: 2.9865x; 1.0590x over previous
#include <cuda_runtime.h>
#include <cstdint>
#include <cstddef>

#define BB 16
#define NN 96
#define DD 256
#define MROWS (BB * NN * NN)          // 147456
#define NCOLS (NN * DD)               // 24576

// Scratch (allocation-free device globals)
__device__ float g_h1[(size_t)MROWS * DD];   // rounded h1
__device__ float g_h2[(size_t)MROWS * DD];   // rounded h2
__device__ float g_W1r[DD * DD];
__device__ float g_W2r[DD * DD];
__device__ float g_Ar[BB * NN * NN];

// ---------------------------------------------------------------------------
// helpers
// ---------------------------------------------------------------------------
__device__ __forceinline__ float tf32r(float x) {
    unsigned u;
    asm("cvt.rna.tf32.f32 %0, %1;" : "=r"(u) : "f"(x));
    return __uint_as_float(u);
}

__device__ __forceinline__ float4 tf32r4(float4 v) {
    v.x = tf32r(v.x); v.y = tf32r(v.y); v.z = tf32r(v.z); v.w = tf32r(v.w);
    return v;
}

__device__ __forceinline__ void mma8(float* c, const unsigned* a, const unsigned* b) {
    asm("mma.sync.aligned.m16n8k8.row.col.f32.tf32.tf32.f32 "
        "{%0,%1,%2,%3}, {%4,%5,%6,%7}, {%8,%9}, {%0,%1,%2,%3};"
        : "+f"(c[0]), "+f"(c[1]), "+f"(c[2]), "+f"(c[3])
        : "r"(a[0]), "r"(a[1]), "r"(a[2]), "r"(a[3]), "r"(b[0]), "r"(b[1]));
}

// ---------------------------------------------------------------------------
// elementwise round-to-tf32 prepass (small tensors only: W1, W2, Aadj)
// ---------------------------------------------------------------------------
__global__ void round_tf32_kernel(const float4* __restrict__ src,
                                  float4* __restrict__ dst, int n4) {
    int i = blockIdx.x * blockDim.x + threadIdx.x;
    if (i < n4) dst[i] = tf32r4(src[i]);
}

// ---------------------------------------------------------------------------
// MLP GEMM: C[M,256] = act(A[M,256] @ W[256,256] + bias), optional row mask.
// BM=128 BN=128 BK=32, 256 threads (8 warps), warp tile 64x32 (4 m16 x 4 n8).
// SMEM: chunk-XOR swizzled, conflict-free fragment LDS.
// roundIn: apply tf32 round-to-nearest to the A operand in the loader
// (used for layer 1, whose A = raw fp32 X).
// ---------------------------------------------------------------------------
__global__ __launch_bounds__(256)
void mlp_mma(const float* __restrict__ A, const float* __restrict__ W,
             const float* __restrict__ bias, const int* __restrict__ mask,
             float* __restrict__ C, int roundOut, int roundIn)
{
    __shared__ float As[128 * 32];   // [m][k], 8 chunks/row, pch = ch ^ (m&7)
    __shared__ float Bs[32 * 128];   // [k][n], 32 chunks/row, pch = ch ^ (k&7)

    const int tid  = threadIdx.x;
    const int lane = tid & 31;
    const int warp = tid >> 5;
    const int grp  = lane >> 2;          // 0..7
    const int c4   = lane & 3;           // 0..3
    const int wm   = warp >> 2;          // 0..1
    const int wn   = warp & 3;           // 0..3
    const int warpM = wm * 64;
    const int warpN = wn * 32;
    const int rowBase = blockIdx.y * 128;
    const int colBase = blockIdx.x * 128;

    // loader indices (4 float4 each for A and B per tile)
    const int ar0 = tid >> 3;            // A row base (+32 per t)
    const int af4 = tid & 7;             // A float4-chunk within row
    const int kr0 = tid >> 5;            // B k-row base (+8 per t)
    const int nf4 = tid & 31;            // B float4-chunk within row

    const int aPch = (af4 ^ (ar0 & 7)) << 2;   // constant per thread
    const int bPch = (nf4 ^ (kr0 & 7)) << 2;

    float4 stA[4], stB[4];

    // prologue LDG (tile 0)
#pragma unroll
    for (int t = 0; t < 4; t++)
        stA[t] = *reinterpret_cast<const float4*>(
            A + (size_t)(rowBase + ar0 + 32 * t) * DD + af4 * 4);
#pragma unroll
    for (int t = 0; t < 4; t++)
        stB[t] = *reinterpret_cast<const float4*>(
            W + (size_t)(kr0 + 8 * t) * DD + colBase + nf4 * 4);

    float acc[4][4][4];
#pragma unroll
    for (int i = 0; i < 4; i++)
#pragma unroll
        for (int j = 0; j < 4; j++)
#pragma unroll
            for (int r = 0; r < 4; r++) acc[i][j][r] = 0.0f;

#pragma unroll 1
    for (int it = 0; it < 8; it++) {
        if (it) __syncthreads();
        // STS staged tile (round A operand here if requested)
#pragma unroll
        for (int t = 0; t < 4; t++) {
            float4 v = roundIn ? tf32r4(stA[t]) : stA[t];
            *reinterpret_cast<float4*>(&As[(ar0 + 32 * t) * 32 + aPch]) = v;
        }
#pragma unroll
        for (int t = 0; t < 4; t++)
            *reinterpret_cast<float4*>(&Bs[(kr0 + 8 * t) * 128 + bPch]) = stB[t];
        __syncthreads();

        // prefetch next tile
        if (it < 7) {
            int kt = (it + 1) * 32;
#pragma unroll
            for (int t = 0; t < 4; t++)
                stA[t] = *reinterpret_cast<const float4*>(
                    A + (size_t)(rowBase + ar0 + 32 * t) * DD + kt + af4 * 4);
#pragma unroll
            for (int t = 0; t < 4; t++)
                stB[t] = *reinterpret_cast<const float4*>(
                    W + (size_t)(kt + kr0 + 8 * t) * DD + colBase + nf4 * 4);
        }

        // compute: 4 k8-steps
#pragma unroll
        for (int s = 0; s < 4; s++) {
            unsigned af[4][4];
#pragma unroll
            for (int mt = 0; mt < 4; mt++) {
                int r  = warpM + mt * 16 + grp;
                int r8 = r + 8;
                af[mt][0] = __float_as_uint(As[r  * 32 + (((2 * s)     ^ (r  & 7)) << 2) + c4]);
                af[mt][1] = __float_as_uint(As[r8 * 32 + (((2 * s)     ^ (r8 & 7)) << 2) + c4]);
                af[mt][2] = __float_as_uint(As[r  * 32 + (((2 * s + 1) ^ (r  & 7)) << 2) + c4]);
                af[mt][3] = __float_as_uint(As[r8 * 32 + (((2 * s + 1) ^ (r8 & 7)) << 2) + c4]);
            }
            unsigned bf[4][2];
#pragma unroll
            for (int nt = 0; nt < 4; nt++) {
                int n  = warpN + nt * 8 + grp;
                int k0 = c4 + 8 * s;
                int k1 = k0 + 4;
                bf[nt][0] = __float_as_uint(Bs[k0 * 128 + (((n >> 2) ^ (k0 & 7)) << 2) + (n & 3)]);
                bf[nt][1] = __float_as_uint(Bs[k1 * 128 + (((n >> 2) ^ (k1 & 7)) << 2) + (n & 3)]);
            }
#pragma unroll
            for (int mt = 0; mt < 4; mt++)
#pragma unroll
                for (int nt = 0; nt < 4; nt++)
                    mma8(acc[mt][nt], af[mt], bf[nt]);
        }
    }

    // epilogue: bias + relu (+mask), optional round-to-tf32 for next layer
#pragma unroll
    for (int mt = 0; mt < 4; mt++) {
        int rr = rowBase + warpM + mt * 16 + grp;
#pragma unroll
        for (int pr = 0; pr < 2; pr++) {
            int r = rr + 8 * pr;
            float mv = 1.0f;
            if (mask != nullptr) mv = (mask[r] != 0) ? 1.0f : 0.0f;
#pragma unroll
            for (int nt = 0; nt < 4; nt++) {
                int col = colBase + warpN + nt * 8 + 2 * c4;
                float2 bb = *reinterpret_cast<const float2*>(bias + col);
                float v0 = fmaxf(acc[mt][nt][2 * pr + 0] + bb.x, 0.0f) * mv;
                float v1 = fmaxf(acc[mt][nt][2 * pr + 1] + bb.y, 0.0f) * mv;
                if (roundOut) { v0 = tf32r(v0); v1 = tf32r(v1); }
                *reinterpret_cast<float2*>(C + (size_t)r * DD + col) = make_float2(v0, v1);
            }
        }
    }
}

// ---------------------------------------------------------------------------
// Message passing: Out[b] (96 x 24576) = Ar[b] (96x96) @ H[b] (96x24576)
// BM=96 (full M), BN=128, BK=32, K=96. 256 threads, warp tile 48x32 (3 m16 x 4 n8).
// ---------------------------------------------------------------------------
__global__ __launch_bounds__(256)
void msg_mma(const float* __restrict__ Ar, const float* __restrict__ H,
             float* __restrict__ Out)
{
    __shared__ float As[96 * 32];
    __shared__ float Bs[32 * 128];

    const int b = blockIdx.y;
    const float* Ab = Ar + (size_t)b * NN * NN;
    const float* Hb = H  + (size_t)b * NN * NCOLS;
    float*       Ob = Out + (size_t)b * NN * NCOLS;

    const int tid  = threadIdx.x;
    const int lane = tid & 31;
    const int warp = tid >> 5;
    const int grp  = lane >> 2;
    const int c4   = lane & 3;
    const int wm   = warp >> 2;          // 0..1
    const int wn   = warp & 3;           // 0..3
    const int warpM = wm * 48;
    const int warpN = wn * 32;
    const int colBase = blockIdx.x * 128;

    const int ar0 = tid >> 3;            // +32 per t, t<3 -> rows 0..95
    const int af4 = tid & 7;
    const int kr0 = tid >> 5;
    const int nf4 = tid & 31;
    const int aPch = (af4 ^ (ar0 & 7)) << 2;
    const int bPch = (nf4 ^ (kr0 & 7)) << 2;

    float4 stA[3], stB[4];
#pragma unroll
    for (int t = 0; t < 3; t++)
        stA[t] = *reinterpret_cast<const float4*>(
            Ab + (size_t)(ar0 + 32 * t) * NN + af4 * 4);
#pragma unroll
    for (int t = 0; t < 4; t++)
        stB[t] = *reinterpret_cast<const float4*>(
            Hb + (size_t)(kr0 + 8 * t) * NCOLS + colBase + nf4 * 4);

    float acc[3][4][4];
#pragma unroll
    for (int i = 0; i < 3; i++)
#pragma unroll
        for (int j = 0; j < 4; j++)
#pragma unroll
            for (int r = 0; r < 4; r++) acc[i][j][r] = 0.0f;

#pragma unroll 1
    for (int it = 0; it < 3; it++) {
        if (it) __syncthreads();
#pragma unroll
        for (int t = 0; t < 3; t++)
            *reinterpret_cast<float4*>(&As[(ar0 + 32 * t) * 32 + aPch]) = stA[t];
#pragma unroll
        for (int t = 0; t < 4; t++)
            *reinterpret_cast<float4*>(&Bs[(kr0 + 8 * t) * 128 + bPch]) = stB[t];
        __syncthreads();

        if (it < 2) {
            int kt = (it + 1) * 32;
#pragma unroll
            for (int t = 0; t < 3; t++)
                stA[t] = *reinterpret_cast<const float4*>(
                    Ab + (size_t)(ar0 + 32 * t) * NN + kt + af4 * 4);
#pragma unroll
            for (int t = 0; t < 4; t++)
                stB[t] = *reinterpret_cast<const float4*>(
                    Hb + (size_t)(kt + kr0 + 8 * t) * NCOLS + colBase + nf4 * 4);
        }

#pragma unroll
        for (int s = 0; s < 4; s++) {
            unsigned af[3][4];
#pragma unroll
            for (int mt = 0; mt < 3; mt++) {
                int r  = warpM + mt * 16 + grp;
                int r8 = r + 8;
                af[mt][0] = __float_as_uint(As[r  * 32 + (((2 * s)     ^ (r  & 7)) << 2) + c4]);
                af[mt][1] = __float_as_uint(As[r8 * 32 + (((2 * s)     ^ (r8 & 7)) << 2) + c4]);
                af[mt][2] = __float_as_uint(As[r  * 32 + (((2 * s + 1) ^ (r  & 7)) << 2) + c4]);
                af[mt][3] = __float_as_uint(As[r8 * 32 + (((2 * s + 1) ^ (r8 & 7)) << 2) + c4]);
            }
            unsigned bf[4][2];
#pragma unroll
            for (int nt = 0; nt < 4; nt++) {
                int n  = warpN + nt * 8 + grp;
                int k0 = c4 + 8 * s;
                int k1 = k0 + 4;
                bf[nt][0] = __float_as_uint(Bs[k0 * 128 + (((n >> 2) ^ (k0 & 7)) << 2) + (n & 3)]);
                bf[nt][1] = __float_as_uint(Bs[k1 * 128 + (((n >> 2) ^ (k1 & 7)) << 2) + (n & 3)]);
            }
#pragma unroll
            for (int mt = 0; mt < 3; mt++)
#pragma unroll
                for (int nt = 0; nt < 4; nt++)
                    mma8(acc[mt][nt], af[mt], bf[nt]);
        }
    }

#pragma unroll
    for (int mt = 0; mt < 3; mt++) {
        int rr = warpM + mt * 16 + grp;
#pragma unroll
        for (int pr = 0; pr < 2; pr++) {
            int r = rr + 8 * pr;
#pragma unroll
            for (int nt = 0; nt < 4; nt++) {
                int col = colBase + warpN + nt * 8 + 2 * c4;
                *reinterpret_cast<float2*>(Ob + (size_t)r * NCOLS + col) =
                    make_float2(acc[mt][nt][2 * pr + 0], acc[mt][nt][2 * pr + 1]);
            }
        }
    }
}

// ---------------------------------------------------------------------------
// kernel_launch: inputs X, mask, A, W1, b1, W2, b2
// ---------------------------------------------------------------------------
extern "C" void kernel_launch(void* const* d_in, const int* in_sizes, int n_in,
                              void* d_out, int out_size)
{
    const float* X    = (const float*)d_in[0];
    const int*   mask = (const int*)d_in[1];
    const float* Aadj = (const float*)d_in[2];
    const float* W1   = (const float*)d_in[3];
    const float* b1   = (const float*)d_in[4];
    const float* W2   = (const float*)d_in[5];
    const float* b2   = (const float*)d_in[6];
    float*       out  = (float*)d_out;

    float *h1, *h2, *w1r, *w2r, *ar;
    cudaGetSymbolAddress((void**)&h1,  g_h1);
    cudaGetSymbolAddress((void**)&h2,  g_h2);
    cudaGetSymbolAddress((void**)&w1r, g_W1r);
    cudaGetSymbolAddress((void**)&w2r, g_W2r);
    cudaGetSymbolAddress((void**)&ar,  g_Ar);

    // tiny prepasses: round W1, W2, Aadj to tf32 (X is rounded in the GEMM loader)
    {
        int w4 = (DD * DD) / 4;
        round_tf32_kernel<<<(w4 + 255) / 256, 256>>>((const float4*)W1, (float4*)w1r, w4);
        round_tf32_kernel<<<(w4 + 255) / 256, 256>>>((const float4*)W2, (float4*)w2r, w4);
        int a4 = (BB * NN * NN) / 4;
        round_tf32_kernel<<<(a4 + 255) / 256, 256>>>((const float4*)Aadj, (float4*)ar, a4);
    }

    // layer 1: h1 = round(relu(round(X) @ W1r + b1))   (X rounded in-loader)
    {
        dim3 grid(DD / 128, MROWS / 128);   // (2, 1152)
        mlp_mma<<<grid, 256>>>(X, w1r, b1, nullptr, h1, 1, 1);
    }
    // layer 2: h2 = round(mask * relu(h1 @ W2r + b2))
    {
        dim3 grid(DD / 128, MROWS / 128);
        mlp_mma<<<grid, 256>>>(h1, w2r, b2, mask, h2, 1, 0);
    }
    // message passing: out[b] = Ar[b] @ h2[b]
    {
        dim3 grid(NCOLS / 128, BB);         // (192, 16)
        msg_mma<<<grid, 256>>>(ar, h2, out);
    }
}

// round 5
// speedup vs baseline: 3.8874x; 1.3017x over previous
#include <cuda_runtime.h>
#include <cstdint>
#include <cstddef>

#define BB 16
#define NN 96
#define DD 256
#define MROWS (BB * NN * NN)          // 147456
#define NCOLS (NN * DD)               // 24576

// Scratch (allocation-free device globals)
__device__ float g_h1[(size_t)MROWS * DD];   // rounded h1
__device__ float g_h2[(size_t)MROWS * DD];   // rounded h2
__device__ float g_W1t[DD * DD];             // transposed+rounded W1: [n][k]
__device__ float g_W2t[DD * DD];             // transposed+rounded W2: [n][k]
__device__ float g_Ar[BB * NN * NN];

// ---------------------------------------------------------------------------
// helpers
// ---------------------------------------------------------------------------
__device__ __forceinline__ float tf32r(float x) {
    unsigned u;
    asm("cvt.rna.tf32.f32 %0, %1;" : "=r"(u) : "f"(x));
    return __uint_as_float(u);
}

__device__ __forceinline__ void mma8(float* c, const unsigned* a, const unsigned* b) {
    asm("mma.sync.aligned.m16n8k8.row.col.f32.tf32.tf32.f32 "
        "{%0,%1,%2,%3}, {%4,%5,%6,%7}, {%8,%9}, {%0,%1,%2,%3};"
        : "+f"(c[0]), "+f"(c[1]), "+f"(c[2]), "+f"(c[3])
        : "r"(a[0]), "r"(a[1]), "r"(a[2]), "r"(a[3]), "r"(b[0]), "r"(b[1]));
}

__device__ __forceinline__ void cpa16(uint32_t dst, const void* src) {
    asm volatile("cp.async.ca.shared.global [%0], [%1], 16;\n" :: "r"(dst), "l"(src));
}
__device__ __forceinline__ void cpa_commit() {
    asm volatile("cp.async.commit_group;\n");
}
template <int N>
__device__ __forceinline__ void cpa_wait() {
    asm volatile("cp.async.wait_group %0;\n" :: "n"(N));
}

// ---------------------------------------------------------------------------
// prepasses
// ---------------------------------------------------------------------------
__global__ void round_tf32_kernel(const float4* __restrict__ src,
                                  float4* __restrict__ dst, int n4) {
    int i = blockIdx.x * blockDim.x + threadIdx.x;
    if (i < n4) {
        float4 v = src[i];
        v.x = tf32r(v.x); v.y = tf32r(v.y); v.z = tf32r(v.z); v.w = tf32r(v.w);
        dst[i] = v;
    }
}

// Wt[n][k] = round(W[k][n]); W is DD x DD. block (32,8), grid (DD/32, DD/32)
__global__ void transpose_round_kernel(const float* __restrict__ src,
                                       float* __restrict__ dst) {
    __shared__ float t[32][33];
    int bx = blockIdx.x * 32;   // n base
    int by = blockIdx.y * 32;   // k base
    int x = threadIdx.x, y0 = threadIdx.y;
#pragma unroll
    for (int r = 0; r < 32; r += 8)
        t[y0 + r][x] = src[(size_t)(by + y0 + r) * DD + bx + x];
    __syncthreads();
#pragma unroll
    for (int r = 0; r < 32; r += 8)
        dst[(size_t)(bx + y0 + r) * DD + by + x] = tf32r(t[x][y0 + r]);
}

// ---------------------------------------------------------------------------
// MLP GEMM: C[M,256] = act(A[M,256] @ W[256,256] + bias), optional row mask.
// BM=128 BN=128 BK=32, 128 threads (4 warps), warp tile 64x64 (4 m16 x 8 n8).
// A smem [m][k], B smem [n][k] (W pre-transposed), both chunk-XOR swizzled ->
// conflict-free fragment LDS on both operands. cp.async double-buffered.
// ROUND_IN: round A fragments to tf32 (layer 1: A = raw X).
// ---------------------------------------------------------------------------
template <int ROUND_IN>
__global__ __launch_bounds__(128)
void mlp_mma2(const float* __restrict__ A, const float* __restrict__ Wt,
              const float* __restrict__ bias, const int* __restrict__ mask,
              float* __restrict__ C, int roundOut)
{
    extern __shared__ float smem[];
    // layout: As[2][4096], Bs[2][4096]  (floats)
    float* AsBase = smem;
    float* BsBase = smem + 8192;

    const int tid  = threadIdx.x;
    const int lane = tid & 31;
    const int warp = tid >> 5;           // 0..3
    const int grp  = lane >> 2;          // 0..7
    const int c4   = lane & 3;           // 0..3
    const int warpM = (warp >> 1) * 64;
    const int warpN = (warp & 1) * 64;
    const int rowBase = blockIdx.y * 128;
    const int colBase = blockIdx.x * 128;

    // loader: per-thread 8 chunks (16B) each for A and B
    const int r0 = tid >> 3;             // row base (+16 per i), 0..15
    const int ch = tid & 7;              // chunk within row

    const uint32_t sAs = (uint32_t)__cvta_generic_to_shared(AsBase);
    const uint32_t sBs = (uint32_t)__cvta_generic_to_shared(BsBase);

    float acc[4][8][4];
#pragma unroll
    for (int i = 0; i < 4; i++)
#pragma unroll
        for (int j = 0; j < 8; j++)
#pragma unroll
            for (int r = 0; r < 4; r++) acc[i][j][r] = 0.0f;

    // per-thread smem byte offsets (stage 0), constant across iters
    uint32_t aOff[8], bOff[8];
#pragma unroll
    for (int i = 0; i < 8; i++) {
        int row = r0 + 16 * i;
        aOff[i] = (uint32_t)((row * 32 + ((ch ^ (row & 7)) << 2)) * 4);
        bOff[i] = aOff[i];               // same scheme for [n][k]
    }

    // prologue: issue stage 0
#pragma unroll
    for (int i = 0; i < 8; i++) {
        int row = r0 + 16 * i;
        cpa16(sAs + aOff[i], A  + (size_t)(rowBase + row) * DD + ch * 4);
        cpa16(sBs + bOff[i], Wt + (size_t)(colBase + row) * DD + ch * 4);
    }
    cpa_commit();

#pragma unroll 1
    for (int it = 0; it < 8; it++) {
        const int stg  = it & 1;
        const uint32_t stB = stg * 16384;         // byte offset of stage
        if (it > 0) __syncthreads();              // prev compute done before reuse

        if (it < 7) {
            const int kt = (it + 1) * 32;
            const uint32_t nstB = ((it + 1) & 1) * 16384;
#pragma unroll
            for (int i = 0; i < 8; i++) {
                int row = r0 + 16 * i;
                cpa16(sAs + nstB + aOff[i], A  + (size_t)(rowBase + row) * DD + kt + ch * 4);
                cpa16(sBs + nstB + bOff[i], Wt + (size_t)(colBase + row) * DD + kt + ch * 4);
            }
            cpa_commit();
            cpa_wait<1>();
        } else {
            cpa_wait<0>();
        }
        __syncthreads();

        const float* As = AsBase + stg * 4096;
        const float* Bs = BsBase + stg * 4096;

#pragma unroll
        for (int s = 0; s < 4; s++) {
            unsigned af[4][4];
#pragma unroll
            for (int mt = 0; mt < 4; mt++) {
                int r  = warpM + mt * 16 + grp;
                int r8 = r + 8;
                float a0 = As[r  * 32 + (((2 * s)     ^ (r  & 7)) << 2) + c4];
                float a1 = As[r8 * 32 + (((2 * s)     ^ (r8 & 7)) << 2) + c4];
                float a2 = As[r  * 32 + (((2 * s + 1) ^ (r  & 7)) << 2) + c4];
                float a3 = As[r8 * 32 + (((2 * s + 1) ^ (r8 & 7)) << 2) + c4];
                if (ROUND_IN) { a0 = tf32r(a0); a1 = tf32r(a1); a2 = tf32r(a2); a3 = tf32r(a3); }
                af[mt][0] = __float_as_uint(a0);
                af[mt][1] = __float_as_uint(a1);
                af[mt][2] = __float_as_uint(a2);
                af[mt][3] = __float_as_uint(a3);
            }
            unsigned bf[8][2];
#pragma unroll
            for (int nt = 0; nt < 8; nt++) {
                int n = warpN + nt * 8 + grp;
                bf[nt][0] = __float_as_uint(Bs[n * 32 + (((2 * s)     ^ (n & 7)) << 2) + c4]);
                bf[nt][1] = __float_as_uint(Bs[n * 32 + (((2 * s + 1) ^ (n & 7)) << 2) + c4]);
            }
#pragma unroll
            for (int mt = 0; mt < 4; mt++)
#pragma unroll
                for (int nt = 0; nt < 8; nt++)
                    mma8(acc[mt][nt], af[mt], bf[nt]);
        }
    }

    // epilogue: bias + relu (+mask), optional round-to-tf32
#pragma unroll
    for (int mt = 0; mt < 4; mt++) {
        int rr = rowBase + warpM + mt * 16 + grp;
#pragma unroll
        for (int pr = 0; pr < 2; pr++) {
            int r = rr + 8 * pr;
            float mv = 1.0f;
            if (mask != nullptr) mv = (mask[r] != 0) ? 1.0f : 0.0f;
#pragma unroll
            for (int nt = 0; nt < 8; nt++) {
                int col = colBase + warpN + nt * 8 + 2 * c4;
                float2 bb = *reinterpret_cast<const float2*>(bias + col);
                float v0 = fmaxf(acc[mt][nt][2 * pr + 0] + bb.x, 0.0f) * mv;
                float v1 = fmaxf(acc[mt][nt][2 * pr + 1] + bb.y, 0.0f) * mv;
                if (roundOut) { v0 = tf32r(v0); v1 = tf32r(v1); }
                *reinterpret_cast<float2*>(C + (size_t)r * DD + col) = make_float2(v0, v1);
            }
        }
    }
}

// ---------------------------------------------------------------------------
// Message passing: Out[b] (96 x 24576) = Ar[b] (96x96) @ H[b] (96x24576)
// BM=96 (full M), BN=128, BK=32, K=96. 256 threads, warp tile 48x32.
// ---------------------------------------------------------------------------
__global__ __launch_bounds__(256)
void msg_mma(const float* __restrict__ Ar, const float* __restrict__ H,
             float* __restrict__ Out)
{
    __shared__ float As[96 * 32];
    __shared__ float Bs[32 * 128];

    const int b = blockIdx.y;
    const float* Ab = Ar + (size_t)b * NN * NN;
    const float* Hb = H  + (size_t)b * NN * NCOLS;
    float*       Ob = Out + (size_t)b * NN * NCOLS;

    const int tid  = threadIdx.x;
    const int lane = tid & 31;
    const int warp = tid >> 5;
    const int grp  = lane >> 2;
    const int c4   = lane & 3;
    const int wm   = warp >> 2;
    const int wn   = warp & 3;
    const int warpM = wm * 48;
    const int warpN = wn * 32;
    const int colBase = blockIdx.x * 128;

    const int ar0 = tid >> 3;
    const int af4 = tid & 7;
    const int kr0 = tid >> 5;
    const int nf4 = tid & 31;
    const int aPch = (af4 ^ (ar0 & 7)) << 2;
    const int bPch = (nf4 ^ (kr0 & 7)) << 2;

    float4 stA[3], stB[4];
#pragma unroll
    for (int t = 0; t < 3; t++)
        stA[t] = *reinterpret_cast<const float4*>(
            Ab + (size_t)(ar0 + 32 * t) * NN + af4 * 4);
#pragma unroll
    for (int t = 0; t < 4; t++)
        stB[t] = *reinterpret_cast<const float4*>(
            Hb + (size_t)(kr0 + 8 * t) * NCOLS + colBase + nf4 * 4);

    float acc[3][4][4];
#pragma unroll
    for (int i = 0; i < 3; i++)
#pragma unroll
        for (int j = 0; j < 4; j++)
#pragma unroll
            for (int r = 0; r < 4; r++) acc[i][j][r] = 0.0f;

#pragma unroll 1
    for (int it = 0; it < 3; it++) {
        if (it) __syncthreads();
#pragma unroll
        for (int t = 0; t < 3; t++)
            *reinterpret_cast<float4*>(&As[(ar0 + 32 * t) * 32 + aPch]) = stA[t];
#pragma unroll
        for (int t = 0; t < 4; t++)
            *reinterpret_cast<float4*>(&Bs[(kr0 + 8 * t) * 128 + bPch]) = stB[t];
        __syncthreads();

        if (it < 2) {
            int kt = (it + 1) * 32;
#pragma unroll
            for (int t = 0; t < 3; t++)
                stA[t] = *reinterpret_cast<const float4*>(
                    Ab + (size_t)(ar0 + 32 * t) * NN + kt + af4 * 4);
#pragma unroll
            for (int t = 0; t < 4; t++)
                stB[t] = *reinterpret_cast<const float4*>(
                    Hb + (size_t)(kt + kr0 + 8 * t) * NCOLS + colBase + nf4 * 4);
        }

#pragma unroll
        for (int s = 0; s < 4; s++) {
            unsigned af[3][4];
#pragma unroll
            for (int mt = 0; mt < 3; mt++) {
                int r  = warpM + mt * 16 + grp;
                int r8 = r + 8;
                af[mt][0] = __float_as_uint(As[r  * 32 + (((2 * s)     ^ (r  & 7)) << 2) + c4]);
                af[mt][1] = __float_as_uint(As[r8 * 32 + (((2 * s)     ^ (r8 & 7)) << 2) + c4]);
                af[mt][2] = __float_as_uint(As[r  * 32 + (((2 * s + 1) ^ (r  & 7)) << 2) + c4]);
                af[mt][3] = __float_as_uint(As[r8 * 32 + (((2 * s + 1) ^ (r8 & 7)) << 2) + c4]);
            }
            unsigned bf[4][2];
#pragma unroll
            for (int nt = 0; nt < 4; nt++) {
                int n  = warpN + nt * 8 + grp;
                int k0 = c4 + 8 * s;
                int k1 = k0 + 4;
                bf[nt][0] = __float_as_uint(Bs[k0 * 128 + (((n >> 2) ^ (k0 & 7)) << 2) + (n & 3)]);
                bf[nt][1] = __float_as_uint(Bs[k1 * 128 + (((n >> 2) ^ (k1 & 7)) << 2) + (n & 3)]);
            }
#pragma unroll
            for (int mt = 0; mt < 3; mt++)
#pragma unroll
                for (int nt = 0; nt < 4; nt++)
                    mma8(acc[mt][nt], af[mt], bf[nt]);
        }
    }

#pragma unroll
    for (int mt = 0; mt < 3; mt++) {
        int rr = warpM + mt * 16 + grp;
#pragma unroll
        for (int pr = 0; pr < 2; pr++) {
            int r = rr + 8 * pr;
#pragma unroll
            for (int nt = 0; nt < 4; nt++) {
                int col = colBase + warpN + nt * 8 + 2 * c4;
                *reinterpret_cast<float2*>(Ob + (size_t)r * NCOLS + col) =
                    make_float2(acc[mt][nt][2 * pr + 0], acc[mt][nt][2 * pr + 1]);
            }
        }
    }
}

// ---------------------------------------------------------------------------
// kernel_launch: inputs X, mask, A, W1, b1, W2, b2
// ---------------------------------------------------------------------------
extern "C" void kernel_launch(void* const* d_in, const int* in_sizes, int n_in,
                              void* d_out, int out_size)
{
    const float* X    = (const float*)d_in[0];
    const int*   mask = (const int*)d_in[1];
    const float* Aadj = (const float*)d_in[2];
    const float* W1   = (const float*)d_in[3];
    const float* b1   = (const float*)d_in[4];
    const float* W2   = (const float*)d_in[5];
    const float* b2   = (const float*)d_in[6];
    float*       out  = (float*)d_out;

    float *h1, *h2, *w1t, *w2t, *ar;
    cudaGetSymbolAddress((void**)&h1,  g_h1);
    cudaGetSymbolAddress((void**)&h2,  g_h2);
    cudaGetSymbolAddress((void**)&w1t, g_W1t);
    cudaGetSymbolAddress((void**)&w2t, g_W2t);
    cudaGetSymbolAddress((void**)&ar,  g_Ar);

    const int MLP_SMEM = 65536;
    cudaFuncSetAttribute(mlp_mma2<1>, cudaFuncAttributeMaxDynamicSharedMemorySize, MLP_SMEM);
    cudaFuncSetAttribute(mlp_mma2<0>, cudaFuncAttributeMaxDynamicSharedMemorySize, MLP_SMEM);

    // prepasses: transpose+round W1/W2, round Aadj
    {
        dim3 tg(DD / 32, DD / 32);
        dim3 tb(32, 8);
        transpose_round_kernel<<<tg, tb>>>(W1, w1t);
        transpose_round_kernel<<<tg, tb>>>(W2, w2t);
        int a4 = (BB * NN * NN) / 4;
        round_tf32_kernel<<<(a4 + 255) / 256, 256>>>((const float4*)Aadj, (float4*)ar, a4);
    }

    // layer 1: h1 = round(relu(round(X) @ W1 + b1))
    {
        dim3 grid(DD / 128, MROWS / 128);   // (2, 1152)
        mlp_mma2<1><<<grid, 128, MLP_SMEM>>>(X, w1t, b1, nullptr, h1, 1);
    }
    // layer 2: h2 = round(mask * relu(h1 @ W2 + b2))
    {
        dim3 grid(DD / 128, MROWS / 128);
        mlp_mma2<0><<<grid, 128, MLP_SMEM>>>(h1, w2t, b2, mask, h2, 1);
    }
    // message passing: out[b] = Ar[b] @ h2[b]
    {
        dim3 grid(NCOLS / 128, BB);         // (192, 16)
        msg_mma<<<grid, 256>>>(ar, h2, out);
    }
}

// round 6
// speedup vs baseline: 4.2918x; 1.1040x over previous
#include <cuda_runtime.h>
#include <cuda_fp16.h>
#include <cstdint>
#include <cstddef>

#define BB 16
#define NN 96
#define DD 256
#define MROWS (BB * NN * NN)          // 147456
#define NCOLS (NN * DD)               // 24576

// Scratch (allocation-free device globals)
__device__ __half g_h1[(size_t)MROWS * DD];
__device__ __half g_h2[(size_t)MROWS * DD];
__device__ __half g_W1h[DD * DD];    // transposed [n][k] fp16
__device__ __half g_W2h[DD * DD];    // transposed [n][k] fp16
__device__ __half g_Ah[BB * NN * NN];

// ---------------------------------------------------------------------------
// helpers
// ---------------------------------------------------------------------------
__device__ __forceinline__ uint32_t packh2(float a, float b) {
    __half2 h = __floats2half2_rn(a, b);
    return *reinterpret_cast<uint32_t*>(&h);
}

__device__ __forceinline__ void mma16(float* c, const uint32_t* a, const uint32_t* b) {
    asm volatile("mma.sync.aligned.m16n8k16.row.col.f32.f16.f16.f32 "
        "{%0,%1,%2,%3}, {%4,%5,%6,%7}, {%8,%9}, {%0,%1,%2,%3};"
        : "+f"(c[0]), "+f"(c[1]), "+f"(c[2]), "+f"(c[3])
        : "r"(a[0]), "r"(a[1]), "r"(a[2]), "r"(a[3]), "r"(b[0]), "r"(b[1]));
}

__device__ __forceinline__ void ldsm4(uint32_t* r, uint32_t addr) {
    asm volatile("ldmatrix.sync.aligned.m8n8.x4.shared.b16 {%0,%1,%2,%3}, [%4];"
        : "=r"(r[0]), "=r"(r[1]), "=r"(r[2]), "=r"(r[3]) : "r"(addr));
}

__device__ __forceinline__ void ldsm4t(uint32_t* r, uint32_t addr) {
    asm volatile("ldmatrix.sync.aligned.m8n8.x4.trans.shared.b16 {%0,%1,%2,%3}, [%4];"
        : "=r"(r[0]), "=r"(r[1]), "=r"(r[2]), "=r"(r[3]) : "r"(addr));
}

__device__ __forceinline__ void cpa16(uint32_t dst, const void* src) {
    asm volatile("cp.async.cg.shared.global [%0], [%1], 16;\n" :: "r"(dst), "l"(src));
}
__device__ __forceinline__ void cpa_commit() {
    asm volatile("cp.async.commit_group;\n");
}
template <int N>
__device__ __forceinline__ void cpa_wait() {
    asm volatile("cp.async.wait_group %0;\n" :: "n"(N));
}

// ---------------------------------------------------------------------------
// prepasses
// ---------------------------------------------------------------------------
// Wh[n][k] = half(W[k][n]); W is DD x DD fp32. block (32,8), grid (DD/32, DD/32)
__global__ void transpose_cvt_kernel(const float* __restrict__ src,
                                     __half* __restrict__ dst) {
    __shared__ float t[32][33];
    int bx = blockIdx.x * 32;   // n base
    int by = blockIdx.y * 32;   // k base
    int x = threadIdx.x, y0 = threadIdx.y;
#pragma unroll
    for (int r = 0; r < 32; r += 8)
        t[y0 + r][x] = src[(size_t)(by + y0 + r) * DD + bx + x];
    __syncthreads();
#pragma unroll
    for (int r = 0; r < 32; r += 8)
        dst[(size_t)(bx + y0 + r) * DD + by + x] = __float2half_rn(t[x][y0 + r]);
}

__global__ void cvt_half_kernel(const float4* __restrict__ src,
                                uint2* __restrict__ dst, int n4) {
    int i = blockIdx.x * blockDim.x + threadIdx.x;
    if (i < n4) {
        float4 v = src[i];
        uint2 o;
        o.x = packh2(v.x, v.y);
        o.y = packh2(v.z, v.w);
        dst[i] = o;
    }
}

// ---------------------------------------------------------------------------
// MLP GEMM: C_half[M,256] = act(A[M,256] @ W + bias), optional row mask.
// BM=128, BN=256 (full D), BK=64, 256 threads (8 warps), warp tile 64x64.
// fp16 smem, m16n8k16 MMA, ldmatrix fragment loads, cp.async double-buffer.
// CONV=1: A is fp32 (X), converted in loader via LDG+cvt+STS register staging.
// CONV=0: A is fp16 (h1), loaded via cp.async.
// smem: As 2 x 16KB (128 rows x 128B), Bs 2 x 32KB (256 rows x 128B), total 96KB.
// ---------------------------------------------------------------------------
template <int CONV>
__global__ __launch_bounds__(256)
void mlp_h(const void* __restrict__ Ain, const __half* __restrict__ Wt,
           const float* __restrict__ bias, const int* __restrict__ mask,
           __half* __restrict__ C)
{
    extern __shared__ __align__(16) char smem[];
    const uint32_t sBase = (uint32_t)__cvta_generic_to_shared(smem);
    const uint32_t aBase = sBase;             // + stage*16384
    const uint32_t bBase = sBase + 32768;     // + stage*32768

    const int tid  = threadIdx.x;
    const int lane = tid & 31;
    const int warp = tid >> 5;
    const int grp  = lane >> 2;
    const int c4   = lane & 3;
    const int warpM = (warp >> 2) * 64;       // 0 / 64
    const int warpN = (warp & 3) * 64;        // 0..192
    const int rowBase = blockIdx.x * 128;

    const float*  Af = (const float*)Ain;
    const __half* Ah = (const __half*)Ain;

    // A loader: row = tid>>1 (0..127), chunks (tid&1)*4 + j (j=0..3), 16B fp16 each
    const int aRow = tid >> 1;
    const int aChB = (tid & 1) * 4;

    uint4 regA[4];   // converted fp16 chunks (CONV path staging)

    float acc[4][8][4];
#pragma unroll
    for (int i = 0; i < 4; i++)
#pragma unroll
        for (int j = 0; j < 8; j++)
#pragma unroll
            for (int r = 0; r < 4; r++) acc[i][j][r] = 0.0f;

    // ---- loader lambdas ----
    auto ldgA = [&](int it) {
#pragma unroll
        for (int j = 0; j < 4; j++) {
            const float* p = Af + (size_t)(rowBase + aRow) * DD + it * 64 + (aChB + j) * 8;
            float4 u = *reinterpret_cast<const float4*>(p);
            float4 v = *reinterpret_cast<const float4*>(p + 4);
            regA[j].x = packh2(u.x, u.y);
            regA[j].y = packh2(u.z, u.w);
            regA[j].z = packh2(v.x, v.y);
            regA[j].w = packh2(v.z, v.w);
        }
    };
    auto stsA = [&](int stage) {
#pragma unroll
        for (int j = 0; j < 4; j++) {
            int ch = aChB + j;
            *reinterpret_cast<uint4*>(smem + stage * 16384 + aRow * 128 +
                                      ((ch ^ (aRow & 7)) << 4)) = regA[j];
        }
    };
    auto cpaA = [&](int it, int stage) {
#pragma unroll
        for (int j = 0; j < 4; j++) {
            int ch = aChB + j;
            cpa16(aBase + stage * 16384 + aRow * 128 + ((ch ^ (aRow & 7)) << 4),
                  Ah + (size_t)(rowBase + aRow) * DD + it * 64 + ch * 8);
        }
    };
    auto cpaB = [&](int it, int stage) {
#pragma unroll
        for (int j = 0; j < 8; j++) {
            cpa16(bBase + stage * 32768 + tid * 128 + ((j ^ (tid & 7)) << 4),
                  Wt + (size_t)tid * DD + it * 64 + j * 8);
        }
    };

    // ---- prologue ----
    if (CONV) {
        cpaB(0, 0); cpa_commit();
        cpaB(1, 1); cpa_commit();
        ldgA(0); stsA(0);
        ldgA(1);                    // regA = A1
    } else {
        cpaA(0, 0); cpaB(0, 0); cpa_commit();
        cpaA(1, 1); cpaB(1, 1); cpa_commit();
    }
    cpa_wait<1>();
    __syncthreads();

    // ---- mainloop: 4 tiles of BK=64 ----
#pragma unroll 1
    for (int it = 0; it < 4; it++) {
        const int s = it & 1;
        const uint32_t aSt = aBase + s * 16384;
        const uint32_t bSt = bBase + s * 32768;

#pragma unroll
        for (int ks = 0; ks < 4; ks++) {      // 4 k16-steps per tile
            uint32_t afr[4][4];
#pragma unroll
            for (int mt = 0; mt < 4; mt++) {
                int m  = warpM + mt * 16 + (lane & 15);
                int ch = 2 * ks + (lane >> 4);
                ldsm4(afr[mt], aSt + m * 128 + ((ch ^ (m & 7)) << 4));
            }
            uint32_t bfr[4][4];
#pragma unroll
            for (int np = 0; np < 4; np++) {
                int n  = warpN + np * 16 + 8 * (lane >> 4) + (lane & 7);
                int ch = 2 * ks + ((lane >> 3) & 1);
                ldsm4(bfr[np], bSt + n * 128 + ((ch ^ (n & 7)) << 4));
            }
#pragma unroll
            for (int mt = 0; mt < 4; mt++)
#pragma unroll
                for (int np = 0; np < 4; np++) {
                    mma16(acc[mt][2 * np + 0], afr[mt], bfr[np] + 0);
                    mma16(acc[mt][2 * np + 1], afr[mt], bfr[np] + 2);
                }
        }
        __syncthreads();                       // all warps done reading stage s

        if (CONV) {
            if (it + 1 <= 3) stsA(s ^ 1);      // A(it+1) from regs
            if (it + 2 <= 3) {
                ldgA(it + 2);
                cpaB(it + 2, s); cpa_commit();
                cpa_wait<1>();
            } else {
                cpa_wait<0>();
            }
        } else {
            if (it + 2 <= 3) {
                cpaA(it + 2, s); cpaB(it + 2, s); cpa_commit();
                cpa_wait<1>();
            } else {
                cpa_wait<0>();
            }
        }
        __syncthreads();
    }

    // ---- epilogue: bias + relu (+mask), store fp16 ----
#pragma unroll
    for (int mt = 0; mt < 4; mt++) {
        int rr = rowBase + warpM + mt * 16 + grp;
#pragma unroll
        for (int pr = 0; pr < 2; pr++) {
            int r = rr + 8 * pr;
            float mv = 1.0f;
            if (mask != nullptr) mv = (mask[r] != 0) ? 1.0f : 0.0f;
#pragma unroll
            for (int nt = 0; nt < 8; nt++) {
                int col = warpN + nt * 8 + 2 * c4;
                float2 bb = *reinterpret_cast<const float2*>(bias + col);
                float v0 = fmaxf(acc[mt][nt][2 * pr + 0] + bb.x, 0.0f) * mv;
                float v1 = fmaxf(acc[mt][nt][2 * pr + 1] + bb.y, 0.0f) * mv;
                *reinterpret_cast<__half2*>(C + (size_t)r * DD + col) =
                    __floats2half2_rn(v0, v1);
            }
        }
    }
}

// ---------------------------------------------------------------------------
// Message passing: Out[b] (96 x 24576 fp32) = Ah[b] (96x96 fp16) @ H[b] (96x24576 fp16)
// 256 threads (8 warps), BN=128 col tile, BK=32 (3 tiles), warp tile 48x32.
// Full A-adj in smem (stride 208B rows, conflict-free ldmatrix).
// B [k][n] smem, fragments via ldmatrix.x4.trans. cp.async double-buffer.
// ---------------------------------------------------------------------------
__global__ __launch_bounds__(256)
void msg_h(const __half* __restrict__ Aall, const __half* __restrict__ H,
           float* __restrict__ Out)
{
    __shared__ __align__(16) char sm[96 * 208 + 2 * 8192];   // 19968 + 16384
    const uint32_t aB = (uint32_t)__cvta_generic_to_shared(sm);
    const uint32_t bB = aB + 19968;

    const int b = blockIdx.y;
    const int colBase = blockIdx.x * 128;
    const __half* Aab = Aall + (size_t)b * NN * NN;
    const __half* Hb  = H    + (size_t)b * NN * NCOLS;
    float*        Ob  = Out  + (size_t)b * NN * NCOLS;

    const int tid  = threadIdx.x;
    const int lane = tid & 31;
    const int warp = tid >> 5;
    const int grp  = lane >> 2;
    const int c4   = lane & 3;
    const int warpM = (warp >> 2) * 48;
    const int warpN = (warp & 3) * 32;

    // B tile loader: krow = tid>>3 (0..31), chunks (tid&7) + 8j (j=0,1)
    const int bkr = tid >> 3;
    const int bch = tid & 7;
    auto cpaBt = [&](int it, int stage) {
#pragma unroll
        for (int j = 0; j < 2; j++) {
            int ch = bch + 8 * j;
            cpa16(bB + stage * 8192 + bkr * 256 + ((ch ^ (bkr & 7)) << 4),
                  Hb + (size_t)(it * 32 + bkr) * NCOLS + colBase + ch * 8);
        }
    };

    // prologue: load all of A-adj + B tiles 0,1
    for (int idx = tid; idx < 96 * 12; idx += 256) {
        int row = idx / 12, ch = idx % 12;
        cpa16(aB + row * 208 + ch * 16, Aab + row * 96 + ch * 8);
    }
    cpaBt(0, 0); cpa_commit();
    cpaBt(1, 1); cpa_commit();
    cpa_wait<1>();
    __syncthreads();

    float acc[3][4][4];
#pragma unroll
    for (int i = 0; i < 3; i++)
#pragma unroll
        for (int j = 0; j < 4; j++)
#pragma unroll
            for (int r = 0; r < 4; r++) acc[i][j][r] = 0.0f;

#pragma unroll 1
    for (int it = 0; it < 3; it++) {
        const int st = it & 1;
#pragma unroll
        for (int sl = 0; sl < 2; sl++) {       // 2 k16-steps per tile
            const int s = 2 * it + sl;         // global k16 step (0..5)
            uint32_t afr[3][4];
#pragma unroll
            for (int mt = 0; mt < 3; mt++) {
                int m  = warpM + mt * 16 + (lane & 15);
                int ch = 2 * s + (lane >> 4);
                ldsm4(afr[mt], aB + m * 208 + ch * 16);
            }
            uint32_t bfr[2][4];
#pragma unroll
            for (int np = 0; np < 2; np++) {
                int kl  = sl * 16 + (lane & 7) + 8 * ((lane >> 3) & 1);
                int chn = (warpN >> 3) + 2 * np + (lane >> 4);
                ldsm4t(bfr[np], bB + st * 8192 + kl * 256 + ((chn ^ (kl & 7)) << 4));
            }
#pragma unroll
            for (int mt = 0; mt < 3; mt++)
#pragma unroll
                for (int np = 0; np < 2; np++) {
                    mma16(acc[mt][2 * np + 0], afr[mt], bfr[np] + 0);
                    mma16(acc[mt][2 * np + 1], afr[mt], bfr[np] + 2);
                }
        }
        __syncthreads();
        if (it + 2 <= 2) {
            cpaBt(it + 2, st); cpa_commit();
            cpa_wait<1>();
        } else {
            cpa_wait<0>();
        }
        __syncthreads();
    }

    // epilogue: fp32 out
#pragma unroll
    for (int mt = 0; mt < 3; mt++) {
        int rr = warpM + mt * 16 + grp;
#pragma unroll
        for (int pr = 0; pr < 2; pr++) {
            int r = rr + 8 * pr;
#pragma unroll
            for (int nt = 0; nt < 4; nt++) {
                int col = colBase + warpN + nt * 8 + 2 * c4;
                *reinterpret_cast<float2*>(Ob + (size_t)r * NCOLS + col) =
                    make_float2(acc[mt][nt][2 * pr + 0], acc[mt][nt][2 * pr + 1]);
            }
        }
    }
}

// ---------------------------------------------------------------------------
// kernel_launch: inputs X, mask, A, W1, b1, W2, b2
// ---------------------------------------------------------------------------
extern "C" void kernel_launch(void* const* d_in, const int* in_sizes, int n_in,
                              void* d_out, int out_size)
{
    const float* X    = (const float*)d_in[0];
    const int*   mask = (const int*)d_in[1];
    const float* Aadj = (const float*)d_in[2];
    const float* W1   = (const float*)d_in[3];
    const float* b1   = (const float*)d_in[4];
    const float* W2   = (const float*)d_in[5];
    const float* b2   = (const float*)d_in[6];
    float*       out  = (float*)d_out;

    __half *h1, *h2, *w1h, *w2h, *ah;
    cudaGetSymbolAddress((void**)&h1,  g_h1);
    cudaGetSymbolAddress((void**)&h2,  g_h2);
    cudaGetSymbolAddress((void**)&w1h, g_W1h);
    cudaGetSymbolAddress((void**)&w2h, g_W2h);
    cudaGetSymbolAddress((void**)&ah,  g_Ah);

    const int MLP_SMEM = 98304;   // 96KB
    cudaFuncSetAttribute(mlp_h<1>, cudaFuncAttributeMaxDynamicSharedMemorySize, MLP_SMEM);
    cudaFuncSetAttribute(mlp_h<0>, cudaFuncAttributeMaxDynamicSharedMemorySize, MLP_SMEM);

    // prepasses: transpose+cvt W1/W2 to fp16 [n][k]; cvt Aadj to fp16
    {
        dim3 tg(DD / 32, DD / 32);
        dim3 tb(32, 8);
        transpose_cvt_kernel<<<tg, tb>>>(W1, w1h);
        transpose_cvt_kernel<<<tg, tb>>>(W2, w2h);
        int a4 = (BB * NN * NN) / 4;
        cvt_half_kernel<<<(a4 + 255) / 256, 256>>>((const float4*)Aadj, (uint2*)ah, a4);
    }

    // layer 1: h1 = half(relu(half(X) @ W1 + b1))
    mlp_h<1><<<MROWS / 128, 256, MLP_SMEM>>>(X, w1h, b1, nullptr, h1);
    // layer 2: h2 = half(mask * relu(h1 @ W2 + b2))
    mlp_h<0><<<MROWS / 128, 256, MLP_SMEM>>>(h1, w2h, b2, mask, h2);
    // message passing: out[b] = Ah[b] @ h2[b]
    {
        dim3 grid(NCOLS / 128, BB);   // (192, 16)
        msg_h<<<grid, 256>>>(ah, h2, out);
    }
}